// round 1
// baseline (speedup 1.0000x reference)
#include <cuda_runtime.h>
#include <math.h>

// ---------------- problem constants ----------------
#define HIDC  256
#define NHEAD 8
#define NN1   60
#define NN2   240
#define NN3   300
#define LLAB  600           // N1+N2+N3
#define DHH   32            // HID/H
#define BBAT  32
#define SSEQ  512
#define DBERT 768
#define NSPLIT 32           // split-K factor for final GEMM

// ---------------- device scratch (no allocation allowed) ----------------
__device__ float g_text_enc[BBAT * SSEQ * HIDC];   // [B,S,HID]
__device__ float g_le      [LLAB * HIDC];
__device__ float g_Kb      [LLAB * HIDC];
__device__ float g_Qb      [LLAB * HIDC];
__device__ float g_Vb      [LLAB * HIDC];
__device__ float g_PAQ     [LLAB * HIDC];
__device__ float g_PMV     [LLAB * HIDC];
__device__ float g_Sc      [NHEAD * LLAB * LLAB];  // [H,L,L]
__device__ float g_M       [LLAB * HIDC];
__device__ float g_aw      [BBAT * LLAB * SSEQ];   // [B,L,S]
__device__ float g_feat    [BBAT * LLAB * HIDC];   // [B,L*HID]
__device__ float g_part    [NSPLIT * BBAT * LLAB]; // split-K partials

static inline int cdiv(int a, int b) { return (a + b - 1) / b; }

// ---------------- generic strided-batched fp32 GEMMs ----------------
// MODE 0: Y = alpha*acc (+ bias[n] if bias)
// MODE 1: Y = tanh(alpha*acc + bias[n])
// MODE 2: Y = tanh(alpha*acc) + res[m,n]      (res may alias Y)

// NT: Y[m,n] = sum_k X[m,k] * W[n,k]
template<int BM, int BN, int BK, int TM, int TN, int MODE>
__global__ void gemm_nt(const float* __restrict__ X, const float* __restrict__ W,
                        const float* __restrict__ bias, const float* __restrict__ res,
                        float* __restrict__ Y,
                        int M, int N, int K,
                        int ldx, int ldw, int ldy,
                        long bsx, long bsw, long bsy, float alpha)
{
    constexpr int NT = (BM / TM) * (BN / TN);
    __shared__ float Xs[BK][BM + 4];
    __shared__ float Ws[BK][BN + 4];

    int bz = blockIdx.z;
    X += bz * bsx; W += bz * bsw; Y += bz * bsy;
    if (MODE == 2) res += bz * bsy;

    int m0 = blockIdx.y * BM, n0 = blockIdx.x * BN;
    int tid = threadIdx.x;
    int tx = tid % (BN / TN), ty = tid / (BN / TN);

    float acc[TM][TN];
    #pragma unroll
    for (int i = 0; i < TM; i++)
        #pragma unroll
        for (int j = 0; j < TN; j++) acc[i][j] = 0.f;

    for (int k0 = 0; k0 < K; k0 += BK) {
        for (int i = tid; i < BM * BK; i += NT) {
            int k = i % BK, m = i / BK;
            int gm = m0 + m, gk = k0 + k;
            Xs[k][m] = (gm < M && gk < K) ? X[(long)gm * ldx + gk] : 0.f;
        }
        for (int i = tid; i < BN * BK; i += NT) {
            int k = i % BK, n = i / BK;
            int gn = n0 + n, gk = k0 + k;
            Ws[k][n] = (gn < N && gk < K) ? W[(long)gn * ldw + gk] : 0.f;
        }
        __syncthreads();
        #pragma unroll
        for (int k = 0; k < BK; k++) {
            float a[TM], b[TN];
            #pragma unroll
            for (int i = 0; i < TM; i++) a[i] = Xs[k][ty * TM + i];
            #pragma unroll
            for (int j = 0; j < TN; j++) b[j] = Ws[k][tx * TN + j];
            #pragma unroll
            for (int i = 0; i < TM; i++)
                #pragma unroll
                for (int j = 0; j < TN; j++) acc[i][j] += a[i] * b[j];
        }
        __syncthreads();
    }

    #pragma unroll
    for (int i = 0; i < TM; i++) {
        int m = m0 + ty * TM + i;
        if (m >= M) continue;
        #pragma unroll
        for (int j = 0; j < TN; j++) {
            int n = n0 + tx * TN + j;
            if (n >= N) continue;
            float v = acc[i][j] * alpha;
            if (MODE == 0)      { if (bias) v += bias[n]; }
            else if (MODE == 1) { v = tanhf(v + bias[n]); }
            else if (MODE == 2) { v = tanhf(v) + res[(long)m * ldy + n]; }
            Y[(long)m * ldy + n] = v;
        }
    }
}

// NN: Y[m,n] = sum_k X[m,k] * W[k,n]
template<int BM, int BN, int BK, int TM, int TN, int MODE>
__global__ void gemm_nn(const float* __restrict__ X, const float* __restrict__ W,
                        const float* __restrict__ bias, const float* __restrict__ res,
                        float* __restrict__ Y,
                        int M, int N, int K,
                        int ldx, int ldw, int ldy,
                        long bsx, long bsw, long bsy, float alpha)
{
    constexpr int NT = (BM / TM) * (BN / TN);
    __shared__ float Xs[BK][BM + 4];
    __shared__ float Ws[BK][BN + 4];

    int bz = blockIdx.z;
    X += bz * bsx; W += bz * bsw; Y += bz * bsy;
    if (MODE == 2) res += bz * bsy;

    int m0 = blockIdx.y * BM, n0 = blockIdx.x * BN;
    int tid = threadIdx.x;
    int tx = tid % (BN / TN), ty = tid / (BN / TN);

    float acc[TM][TN];
    #pragma unroll
    for (int i = 0; i < TM; i++)
        #pragma unroll
        for (int j = 0; j < TN; j++) acc[i][j] = 0.f;

    for (int k0 = 0; k0 < K; k0 += BK) {
        for (int i = tid; i < BM * BK; i += NT) {
            int k = i % BK, m = i / BK;
            int gm = m0 + m, gk = k0 + k;
            Xs[k][m] = (gm < M && gk < K) ? X[(long)gm * ldx + gk] : 0.f;
        }
        for (int i = tid; i < BK * BN; i += NT) {
            int n = i % BN, k = i / BN;
            int gn = n0 + n, gk = k0 + k;
            Ws[k][n] = (gn < N && gk < K) ? W[(long)gk * ldw + gn] : 0.f;
        }
        __syncthreads();
        #pragma unroll
        for (int k = 0; k < BK; k++) {
            float a[TM], b[TN];
            #pragma unroll
            for (int i = 0; i < TM; i++) a[i] = Xs[k][ty * TM + i];
            #pragma unroll
            for (int j = 0; j < TN; j++) b[j] = Ws[k][tx * TN + j];
            #pragma unroll
            for (int i = 0; i < TM; i++)
                #pragma unroll
                for (int j = 0; j < TN; j++) acc[i][j] += a[i] * b[j];
        }
        __syncthreads();
    }

    #pragma unroll
    for (int i = 0; i < TM; i++) {
        int m = m0 + ty * TM + i;
        if (m >= M) continue;
        #pragma unroll
        for (int j = 0; j < TN; j++) {
            int n = n0 + tx * TN + j;
            if (n >= N) continue;
            float v = acc[i][j] * alpha;
            if (MODE == 0)      { if (bias) v += bias[n]; }
            else if (MODE == 1) { v = tanhf(v + bias[n]); }
            else if (MODE == 2) { v = tanhf(v) + res[(long)m * ldy + n]; }
            Y[(long)m * ldy + n] = v;
        }
    }
}

// ---------------- attention softmax (HGT layer) ----------------
// In-place on g_Sc[h,q,:]. Replicates:
//   logit = (Z ? 0 : Sc) + (amask==0 ? -inf : 0)
//   p = softmax(logit); p *= (1 - Z)
__global__ void attn_softmax(float* __restrict__ Sc, const int* __restrict__ amask)
{
    const int q = blockIdx.x, h = blockIdx.y;
    float* row = Sc + ((long)h * LLAB + q) * LLAB;
    const int* mrow = amask + (long)q * LLAB;

    __shared__ float buf[LLAB];
    __shared__ float red[33];
    const int tid = threadIdx.x;          // 128 threads
    const bool qb1 = (q < NN1), qb3 = (q >= NN1 + NN2);

    float mx = -INFINITY;
    for (int k = tid; k < LLAB; k += 128) {
        bool kb1 = (k < NN1), kb3 = (k >= NN1 + NN2);
        bool Z = (qb1 && kb3) || (qb3 && kb1);
        float mk = (mrow[k] == 0) ? -INFINITY : 0.f;
        float v = (Z ? 0.f : row[k]) + mk;
        buf[k] = v;
        mx = fmaxf(mx, v);
    }
    // block-reduce max
    for (int o = 16; o; o >>= 1) mx = fmaxf(mx, __shfl_xor_sync(0xffffffffu, mx, o));
    if ((tid & 31) == 0) red[tid >> 5] = mx;
    __syncthreads();
    if (tid < 32) {
        float t = (tid < 4) ? red[tid] : -INFINITY;
        for (int o = 16; o; o >>= 1) t = fmaxf(t, __shfl_xor_sync(0xffffffffu, t, o));
        if (tid == 0) red[32] = t;
    }
    __syncthreads();
    mx = red[32];
    __syncthreads();

    float sum = 0.f;
    for (int k = tid; k < LLAB; k += 128) {
        float e = expf(buf[k] - mx);
        buf[k] = e;
        sum += e;
    }
    for (int o = 16; o; o >>= 1) sum += __shfl_xor_sync(0xffffffffu, sum, o);
    if ((tid & 31) == 0) red[tid >> 5] = sum;
    __syncthreads();
    if (tid < 32) {
        float t = (tid < 4) ? red[tid] : 0.f;
        for (int o = 16; o; o >>= 1) t += __shfl_xor_sync(0xffffffffu, t, o);
        if (tid == 0) red[32] = t;
    }
    __syncthreads();
    float inv = 1.f / red[32];

    for (int k = tid; k < LLAB; k += 128) {
        bool kb1 = (k < NN1), kb3 = (k >= NN1 + NN2);
        bool Z = (qb1 && kb3) || (qb3 && kb1);
        row[k] = Z ? 0.f : buf[k] * inv;
    }
}

// ---------------- pooling softmax over S with pad mask ----------------
__global__ void pool_softmax(float* __restrict__ aw, const int* __restrict__ tok)
{
    const int l = blockIdx.x, b = blockIdx.y;
    float* row = aw + ((long)b * LLAB + l) * SSEQ;
    const int* t = tok + (long)b * SSEQ;

    __shared__ float buf[SSEQ];
    __shared__ float red[33];
    const int tid = threadIdx.x;   // 256 threads

    float mx = -INFINITY;
    for (int s = tid; s < SSEQ; s += 256) {
        int tv = t[s];
        bool bad = (tv == 0) || (tv == 101) || (tv == 102);
        float v = row[s] + (bad ? -INFINITY : 0.f);
        buf[s] = v;
        mx = fmaxf(mx, v);
    }
    for (int o = 16; o; o >>= 1) mx = fmaxf(mx, __shfl_xor_sync(0xffffffffu, mx, o));
    if ((tid & 31) == 0) red[tid >> 5] = mx;
    __syncthreads();
    if (tid < 32) {
        float v = (tid < 8) ? red[tid] : -INFINITY;
        for (int o = 16; o; o >>= 1) v = fmaxf(v, __shfl_xor_sync(0xffffffffu, v, o));
        if (tid == 0) red[32] = v;
    }
    __syncthreads();
    mx = red[32];
    __syncthreads();

    float sum = 0.f;
    for (int s = tid; s < SSEQ; s += 256) {
        float e = expf(buf[s] - mx);
        buf[s] = e;
        sum += e;
    }
    for (int o = 16; o; o >>= 1) sum += __shfl_xor_sync(0xffffffffu, sum, o);
    if ((tid & 31) == 0) red[tid >> 5] = sum;
    __syncthreads();
    if (tid < 32) {
        float v = (tid < 8) ? red[tid] : 0.f;
        for (int o = 16; o; o >>= 1) v += __shfl_xor_sync(0xffffffffu, v, o);
        if (tid == 0) red[32] = v;
    }
    __syncthreads();
    float inv = 1.f / red[32];

    for (int s = tid; s < SSEQ; s += 256) row[s] = buf[s] * inv;
}

// ---------------- final split-K reduce + sigmoid ----------------
__global__ void final_reduce(const float* __restrict__ part,
                             const float* __restrict__ bout,
                             float* __restrict__ out)
{
    int i = blockIdx.x * blockDim.x + threadIdx.x;  // over B*L
    if (i >= BBAT * LLAB) return;
    int l = i % LLAB;
    float s = bout[l];
    #pragma unroll
    for (int z = 0; z < NSPLIT; z++) s += part[z * (BBAT * LLAB) + i];
    out[i] = 1.f / (1.f + expf(-s));
}

// ---------------- host orchestration ----------------
extern "C" void kernel_launch(void* const* d_in, const int* in_sizes, int n_in,
                              void* d_out, int out_size)
{
    const int*   inputs      = (const int*)  d_in[0];
    const float* text_hidden = (const float*)d_in[1];
    const float* label_feat  = (const float*)d_in[2];
    const int*   amask       = (const int*)  d_in[3];
    const float* Wt   = (const float*)d_in[4];
    const float* bt   = (const float*)d_in[5];
    const float* Wl   = (const float*)d_in[6];
    const float* bl   = (const float*)d_in[7];
    const float* WK   = (const float*)d_in[8];
    const float* WQ   = (const float*)d_in[9];
    const float* WV   = (const float*)d_in[10];
    const float* PA   = (const float*)d_in[11];
    const float* PM   = (const float*)d_in[12];
    const float* WA   = (const float*)d_in[13];
    const float* Wout = (const float*)d_in[14];
    const float* bout = (const float*)d_in[15];
    float* out = (float*)d_out;

    float *te, *le, *Kb, *Qb, *Vb, *paq, *pmv, *sc, *mm, *aw, *feat, *part;
    cudaGetSymbolAddress((void**)&te,   g_text_enc);
    cudaGetSymbolAddress((void**)&le,   g_le);
    cudaGetSymbolAddress((void**)&Kb,   g_Kb);
    cudaGetSymbolAddress((void**)&Qb,   g_Qb);
    cudaGetSymbolAddress((void**)&Vb,   g_Vb);
    cudaGetSymbolAddress((void**)&paq,  g_PAQ);
    cudaGetSymbolAddress((void**)&pmv,  g_PMV);
    cudaGetSymbolAddress((void**)&sc,   g_Sc);
    cudaGetSymbolAddress((void**)&mm,   g_M);
    cudaGetSymbolAddress((void**)&aw,   g_aw);
    cudaGetSymbolAddress((void**)&feat, g_feat);
    cudaGetSymbolAddress((void**)&part, g_part);

    const float scale = 1.f / sqrtf((float)DHH);
    const int starts[3] = {0, NN1, NN1 + NN2};
    const int counts[3] = {NN1, NN2, NN3};

    // text_enc = tanh(text_hidden @ Wt^T + bt)   [16384, 256]
    gemm_nt<64,64,16,4,4,1><<<dim3(cdiv(HIDC,64), cdiv(BBAT*SSEQ,64), 1), 256>>>(
        text_hidden, Wt, bt, nullptr, te,
        BBAT*SSEQ, HIDC, DBERT, DBERT, DBERT, HIDC, 0, 0, 0, 1.f);

    // le = label_feat @ Wl^T + bl   [600, 256]
    gemm_nt<64,64,16,4,4,0><<<dim3(cdiv(HIDC,64), cdiv(LLAB,64), 1), 256>>>(
        label_feat, Wl, bl, nullptr, le,
        LLAB, HIDC, DBERT, DBERT, DBERT, HIDC, 0, 0, 0, 1.f);

    for (int layer = 0; layer < 2; layer++) {
        // per-type K/Q/V projections
        for (int t = 0; t < 3; t++) {
            int s0 = starts[t], cnt = counts[t];
            const float* wk = WK + (long)t * HIDC * HIDC;
            const float* wq = WQ + (long)t * HIDC * HIDC;
            const float* wv = WV + (long)t * HIDC * HIDC;
            dim3 g(cdiv(HIDC,64), cdiv(cnt,64), 1);
            gemm_nt<64,64,16,4,4,0><<<g,256>>>(le + (long)s0*HIDC, wk, nullptr, nullptr,
                Kb + (long)s0*HIDC, cnt, HIDC, HIDC, HIDC, HIDC, HIDC, 0,0,0, 1.f);
            gemm_nt<64,64,16,4,4,0><<<g,256>>>(le + (long)s0*HIDC, wq, nullptr, nullptr,
                Qb + (long)s0*HIDC, cnt, HIDC, HIDC, HIDC, HIDC, HIDC, 0,0,0, 1.f);
            gemm_nt<64,64,16,4,4,0><<<g,256>>>(le + (long)s0*HIDC, wv, nullptr, nullptr,
                Vb + (long)s0*HIDC, cnt, HIDC, HIDC, HIDC, HIDC, HIDC, 0,0,0, 1.f);
        }

        // PAQ[(l,h),:] = Q[(l,h),:] @ PA^T ; PMV analog   [4800, 32] x [32,32]
        gemm_nt<64,32,16,4,2,0><<<dim3(1, cdiv(LLAB*NHEAD,64), 1), 256>>>(
            Qb, PA, nullptr, nullptr, paq,
            LLAB*NHEAD, DHH, DHH, DHH, DHH, DHH, 0,0,0, 1.f);
        gemm_nt<64,32,16,4,2,0><<<dim3(1, cdiv(LLAB*NHEAD,64), 1), 256>>>(
            Vb, PM, nullptr, nullptr, pmv,
            LLAB*NHEAD, DHH, DHH, DHH, DHH, DHH, 0,0,0, 1.f);

        // Sc[h,q,k] = scale * sum_d PAQ[q,h,d] * K[k,h,d]  (batched over h)
        gemm_nt<64,64,16,4,4,0><<<dim3(cdiv(LLAB,64), cdiv(LLAB,64), NHEAD), 256>>>(
            paq, Kb, nullptr, nullptr, sc,
            LLAB, LLAB, DHH, HIDC, HIDC, LLAB,
            DHH, DHH, (long)LLAB*LLAB, scale);

        // masked softmax (+ zero-block semantics) in place
        attn_softmax<<<dim3(LLAB, NHEAD), 128>>>(sc, amask);

        // M[q, h*32+e] = sum_k Watt[h,q,k] * PMV[k, h*32+e]  (batched over h)
        gemm_nn<64,32,16,4,2,0><<<dim3(1, cdiv(LLAB,64), NHEAD), 256>>>(
            sc, pmv, nullptr, nullptr, mm,
            LLAB, DHH, LLAB, LLAB, HIDC, HIDC,
            (long)LLAB*LLAB, DHH, DHH, 1.f);

        // le = tanh(per_type(M, WA)) + le
        for (int t = 0; t < 3; t++) {
            int s0 = starts[t], cnt = counts[t];
            const float* wa = WA + (long)t * HIDC * HIDC;
            gemm_nt<64,64,16,4,4,2><<<dim3(cdiv(HIDC,64), cdiv(cnt,64), 1), 256>>>(
                mm + (long)s0*HIDC, wa, nullptr, le + (long)s0*HIDC,
                le + (long)s0*HIDC, cnt, HIDC, HIDC, HIDC, HIDC, HIDC, 0,0,0, 1.f);
        }
    }

    // aw[b,l,s] = sum_e le[l,e] * text_enc[b,s,e]   (batched over b)
    gemm_nt<64,64,16,4,4,0><<<dim3(cdiv(SSEQ,64), cdiv(LLAB,64), BBAT), 256>>>(
        le, te, nullptr, nullptr, aw,
        LLAB, SSEQ, HIDC, HIDC, HIDC, SSEQ,
        0, (long)SSEQ*HIDC, (long)LLAB*SSEQ, 1.f);

    // softmax over s with pad mask
    pool_softmax<<<dim3(LLAB, BBAT), 256>>>(aw, inputs);

    // features[b,l,e] = sum_s aw[b,l,s] * text_enc[b,s,e]   (batched over b)
    gemm_nn<64,64,16,4,4,0><<<dim3(cdiv(HIDC,64), cdiv(LLAB,64), BBAT), 256>>>(
        aw, te, nullptr, nullptr, feat,
        LLAB, HIDC, SSEQ, SSEQ, HIDC, HIDC,
        (long)LLAB*SSEQ, (long)SSEQ*HIDC, (long)LLAB*HIDC, 1.f);

    // final GEMM, split-K over z: part[z][b][l] = sum_{k in split z} feat[b,k]*Wout[l,k]
    {
        const int KS = (LLAB * HIDC) / NSPLIT;   // 4800
        gemm_nt<32,64,16,2,4,0><<<dim3(cdiv(LLAB,64), 1, NSPLIT), 256>>>(
            feat, Wout, nullptr, nullptr, part,
            BBAT, LLAB, KS,
            LLAB*HIDC, LLAB*HIDC, LLAB,
            (long)KS, (long)KS, (long)BBAT*LLAB, 1.f);
    }

    // out[b,l] = sigmoid(sum_z part + bout[l])
    final_reduce<<<cdiv(BBAT*LLAB, 256), 256>>>(part, bout, out);
}

// round 3
// speedup vs baseline: 1.8186x; 1.8186x over previous
#include <cuda_runtime.h>
#include <math.h>

// ---------------- problem constants ----------------
#define HIDC  256
#define NHEAD 8
#define NN1   60
#define NN2   240
#define NN3   300
#define LLAB  600           // N1+N2+N3
#define DHH   32            // HID/H
#define BBAT  32
#define SSEQ  512
#define DBERT 768
#define NSPLIT 64           // split-K factor for final GEMM

// ---------------- device scratch (no allocation allowed) ----------------
__device__ float g_text_enc[BBAT * SSEQ * HIDC];   // [B,S,HID]
__device__ float g_le      [LLAB * HIDC];
__device__ float g_Kb      [LLAB * HIDC];
__device__ float g_PAQ     [LLAB * HIDC];
__device__ float g_PMV     [LLAB * HIDC];
__device__ float g_Sc      [NHEAD * LLAB * LLAB];  // [H,L,L]
__device__ float g_M       [LLAB * HIDC];
__device__ float g_aw      [BBAT * LLAB * SSEQ];   // [B,L,S]
__device__ float g_feat    [BBAT * LLAB * HIDC];   // [B,L*HID]
__device__ float g_part    [NSPLIT * BBAT * LLAB]; // split-K partials
__device__ float g_WQe     [3 * HIDC * HIDC];      // blockdiag(PA) @ WQ
__device__ float g_WVe     [3 * HIDC * HIDC];      // blockdiag(PM) @ WV

static inline int cdiv(int a, int b) { return (a + b - 1) / b; }

// =====================================================================
// Generic 64/32-tile fp32 GEMM body (device function, shared by wrappers)
// MODE 0: Y = alpha*acc (+ bias[n] if bias)
// MODE 2: Y = tanh(alpha*acc) + res[m,n]
// TRANS_W=false: NT  Y[m,n] = sum_k X[m,k]*W[n,k]
// TRANS_W=true : NN  Y[m,n] = sum_k X[m,k]*W[k,n]
// =====================================================================
template<int BM, int BN, int BK, int TM, int TN, int MODE, bool TRANS_W>
__device__ __forceinline__ void gemm_dev(
    const float* __restrict__ X, const float* __restrict__ W,
    const float* __restrict__ bias, const float* __restrict__ res,
    float* __restrict__ Y,
    int M, int N, int K, int ldx, int ldw, int ldy, float alpha)
{
    constexpr int NT = (BM / TM) * (BN / TN);
    __shared__ float Xs[BK][BM + 4];
    __shared__ float Ws[BK][BN + 4];

    int m0 = blockIdx.y * BM, n0 = blockIdx.x * BN;
    int tid = threadIdx.x;
    int tx = tid % (BN / TN), ty = tid / (BN / TN);

    float acc[TM][TN];
    #pragma unroll
    for (int i = 0; i < TM; i++)
        #pragma unroll
        for (int j = 0; j < TN; j++) acc[i][j] = 0.f;

    for (int k0 = 0; k0 < K; k0 += BK) {
        for (int i = tid; i < BM * BK; i += NT) {
            int k = i % BK, m = i / BK;
            int gm = m0 + m, gk = k0 + k;
            Xs[k][m] = (gm < M && gk < K) ? X[(long)gm * ldx + gk] : 0.f;
        }
        if (!TRANS_W) {
            for (int i = tid; i < BN * BK; i += NT) {
                int k = i % BK, n = i / BK;
                int gn = n0 + n, gk = k0 + k;
                Ws[k][n] = (gn < N && gk < K) ? W[(long)gn * ldw + gk] : 0.f;
            }
        } else {
            for (int i = tid; i < BK * BN; i += NT) {
                int n = i % BN, k = i / BN;
                int gn = n0 + n, gk = k0 + k;
                Ws[k][n] = (gn < N && gk < K) ? W[(long)gk * ldw + gn] : 0.f;
            }
        }
        __syncthreads();
        #pragma unroll
        for (int k = 0; k < BK; k++) {
            float a[TM], b[TN];
            #pragma unroll
            for (int i = 0; i < TM; i++) a[i] = Xs[k][ty * TM + i];
            #pragma unroll
            for (int j = 0; j < TN; j++) b[j] = Ws[k][tx * TN + j];
            #pragma unroll
            for (int i = 0; i < TM; i++)
                #pragma unroll
                for (int j = 0; j < TN; j++) acc[i][j] += a[i] * b[j];
        }
        __syncthreads();
    }

    #pragma unroll
    for (int i = 0; i < TM; i++) {
        int m = m0 + ty * TM + i;
        if (m >= M) continue;
        #pragma unroll
        for (int j = 0; j < TN; j++) {
            int n = n0 + tx * TN + j;
            if (n >= N) continue;
            float v = acc[i][j] * alpha;
            if (MODE == 0)      { if (bias) v += bias[n]; }
            else if (MODE == 2) { v = tanhf(v) + res[(long)m * ldy + n]; }
            Y[(long)m * ldy + n] = v;
        }
    }
}

// generic strided-batched wrapper
template<int BM, int BN, int BK, int TM, int TN, int MODE, bool TRANS_W>
__global__ void gemm_g(const float* __restrict__ X, const float* __restrict__ W,
                       const float* __restrict__ bias, const float* __restrict__ res,
                       float* __restrict__ Y,
                       int M, int N, int K, int ldx, int ldw, int ldy,
                       long bsx, long bsw, long bsy, float alpha)
{
    int bz = blockIdx.z;
    gemm_dev<BM, BN, BK, TM, TN, MODE, TRANS_W>(
        X + bz * bsx, W + bz * bsw, bias,
        (MODE == 2) ? (res + bz * bsy) : res,
        Y + bz * bsy, M, N, K, ldx, ldw, ldy, alpha);
}

// =====================================================================
// 128x128x8 vectorized fp32 GEMM for the big matmuls
// MODE 0: Y = acc (+bias) ; MODE 1: Y = tanh(acc + bias)
// =====================================================================
template<int MODE, bool TRANS_W>
__global__ void sgemm128(const float* __restrict__ Xg, const float* __restrict__ Wg,
                         const float* __restrict__ bias, float* __restrict__ Yg,
                         int M, int N, int K, int ldx, int ldw, int ldy,
                         long bsx, long bsw, long bsy)
{
    constexpr int BK = 8;
    __shared__ float Xs[BK][132];
    __shared__ float Ws[BK][132];

    const float* X = Xg + blockIdx.z * bsx;
    const float* W = Wg + blockIdx.z * bsw;
    float* Y = Yg + blockIdx.z * bsy;

    int m0 = blockIdx.y * 128, n0 = blockIdx.x * 128;
    int tid = threadIdx.x;           // 256 threads
    int tx = tid & 15, ty = tid >> 4;

    float acc[8][8];
    #pragma unroll
    for (int i = 0; i < 8; i++)
        #pragma unroll
        for (int j = 0; j < 8; j++) acc[i][j] = 0.f;

    for (int k0 = 0; k0 < K; k0 += BK) {
        {   // X tile [128 x 8], row-major [M,K]
            int row = tid >> 1, part = (tid & 1) * 4;
            int gm = m0 + row;
            float4 v = make_float4(0.f, 0.f, 0.f, 0.f);
            if (gm < M) v = *(const float4*)(X + (long)gm * ldx + k0 + part);
            Xs[part + 0][row] = v.x; Xs[part + 1][row] = v.y;
            Xs[part + 2][row] = v.z; Xs[part + 3][row] = v.w;
        }
        if (!TRANS_W) {  // W [N,K] row-major
            int row = tid >> 1, part = (tid & 1) * 4;
            int gn = n0 + row;
            float4 v = make_float4(0.f, 0.f, 0.f, 0.f);
            if (gn < N) v = *(const float4*)(W + (long)gn * ldw + k0 + part);
            Ws[part + 0][row] = v.x; Ws[part + 1][row] = v.y;
            Ws[part + 2][row] = v.z; Ws[part + 3][row] = v.w;
        } else {         // W [K,N] row-major
            int k = tid >> 5, n4 = (tid & 31) * 4;
            int gn = n0 + n4;
            float4 v = make_float4(0.f, 0.f, 0.f, 0.f);
            if (gn < N) v = *(const float4*)(W + (long)(k0 + k) * ldw + gn);
            *(float4*)&Ws[k][n4] = v;
        }
        __syncthreads();
        #pragma unroll
        for (int k = 0; k < BK; k++) {
            float a[8], b[8];
            #pragma unroll
            for (int i = 0; i < 8; i++) a[i] = Xs[k][ty * 8 + i];
            #pragma unroll
            for (int j = 0; j < 8; j++) b[j] = Ws[k][tx * 8 + j];
            #pragma unroll
            for (int i = 0; i < 8; i++)
                #pragma unroll
                for (int j = 0; j < 8; j++) acc[i][j] += a[i] * b[j];
        }
        __syncthreads();
    }

    #pragma unroll
    for (int i = 0; i < 8; i++) {
        int m = m0 + ty * 8 + i;
        if (m >= M) continue;
        #pragma unroll
        for (int j = 0; j < 8; j++) {
            int n = n0 + tx * 8 + j;
            if (n >= N) continue;
            float v = acc[i][j];
            if (MODE == 0)      { if (bias) v += bias[n]; }
            else if (MODE == 1) { v = tanhf(v + bias[n]); }
            Y[(long)m * ldy + n] = v;
        }
    }
}

// =====================================================================
// Effective weights: WQe[t][h*32+e][c] = sum_d PA[e][d] * WQ[t][h*32+d][c]
// grid (24, 2): x = t*8+h, y: 0=Q/PA, 1=V/PM. 256 threads.
// =====================================================================
__global__ void prep_eff(const float* __restrict__ WQ, const float* __restrict__ WV,
                         const float* __restrict__ PA, const float* __restrict__ PM,
                         float* __restrict__ WQe, float* __restrict__ WVe)
{
    int t = blockIdx.x >> 3, h = blockIdx.x & 7;
    const float* W = (blockIdx.y == 0 ? WQ : WV) + (long)t * HIDC * HIDC + (long)h * DHH * HIDC;
    const float* P = (blockIdx.y == 0 ? PA : PM);
    float* O = (blockIdx.y == 0 ? WQe : WVe) + (long)t * HIDC * HIDC + (long)h * DHH * HIDC;

    __shared__ float Ps[DHH][DHH];
    int tid = threadIdx.x;
    for (int i = tid; i < DHH * DHH; i += 256) Ps[i / DHH][i % DHH] = P[i];
    __syncthreads();

    int c = tid;  // 0..255 columns
    float w[DHH];
    #pragma unroll
    for (int d = 0; d < DHH; d++) w[d] = W[(long)d * HIDC + c];
    #pragma unroll
    for (int e = 0; e < DHH; e++) {
        float s = 0.f;
        #pragma unroll
        for (int d = 0; d < DHH; d++) s += Ps[e][d] * w[d];
        O[(long)e * HIDC + c] = s;
    }
}

// =====================================================================
// Fused per-type projections: one launch computes K, PAQ, PMV for all 3 types.
// grid (4, 5, 9); z = which*3 + t
// =====================================================================
__global__ void proj_fused(const float* __restrict__ le,
                           const float* __restrict__ WK,
                           const float* __restrict__ WQe,
                           const float* __restrict__ WVe,
                           float* __restrict__ Kb, float* __restrict__ PAQ,
                           float* __restrict__ PMV)
{
    int z = blockIdx.z;
    int t = z % 3, which = z / 3;
    int s0 = (t == 0) ? 0 : (t == 1 ? NN1 : NN1 + NN2);
    int cnt = (t == 0) ? NN1 : (t == 1 ? NN2 : NN3);
    if ((int)blockIdx.y * 64 >= cnt) return;
    const float* W = (which == 0 ? WK : (which == 1 ? WQe : WVe)) + (long)t * HIDC * HIDC;
    float* Y = (which == 0 ? Kb : (which == 1 ? PAQ : PMV)) + (long)s0 * HIDC;
    gemm_dev<64, 64, 16, 4, 4, 0, false>(
        le + (long)s0 * HIDC, W, nullptr, nullptr, Y,
        cnt, HIDC, HIDC, HIDC, HIDC, HIDC, 1.f);
}

// Fused WA epilogue: le = tanh(per_type(M, WA)) + le. grid (4, 5, 3)
__global__ void wa_fused(const float* __restrict__ Mm, const float* __restrict__ WA,
                         float* __restrict__ le)
{
    int t = blockIdx.z;
    int s0 = (t == 0) ? 0 : (t == 1 ? NN1 : NN1 + NN2);
    int cnt = (t == 0) ? NN1 : (t == 1 ? NN2 : NN3);
    if ((int)blockIdx.y * 64 >= cnt) return;
    gemm_dev<64, 64, 16, 4, 4, 2, false>(
        Mm + (long)s0 * HIDC, WA + (long)t * HIDC * HIDC, nullptr,
        le + (long)s0 * HIDC, le + (long)s0 * HIDC,
        cnt, HIDC, HIDC, HIDC, HIDC, HIDC, 1.f);
}

// =====================================================================
// Attention softmax with zero-block + additive mask semantics (in-place)
// =====================================================================
__global__ void attn_softmax(float* __restrict__ Sc, const int* __restrict__ amask)
{
    const int q = blockIdx.x, h = blockIdx.y;
    float* row = Sc + ((long)h * LLAB + q) * LLAB;
    const int* mrow = amask + (long)q * LLAB;

    __shared__ float buf[LLAB];
    __shared__ float red[33];
    const int tid = threadIdx.x;          // 128 threads
    const bool qb1 = (q < NN1), qb3 = (q >= NN1 + NN2);

    float mx = -INFINITY;
    for (int k = tid; k < LLAB; k += 128) {
        bool kb1 = (k < NN1), kb3 = (k >= NN1 + NN2);
        bool Z = (qb1 && kb3) || (qb3 && kb1);
        float mk = (mrow[k] == 0) ? -INFINITY : 0.f;
        float v = (Z ? 0.f : row[k]) + mk;
        buf[k] = v;
        mx = fmaxf(mx, v);
    }
    for (int o = 16; o; o >>= 1) mx = fmaxf(mx, __shfl_xor_sync(0xffffffffu, mx, o));
    if ((tid & 31) == 0) red[tid >> 5] = mx;
    __syncthreads();
    if (tid < 32) {
        float t = (tid < 4) ? red[tid] : -INFINITY;
        for (int o = 16; o; o >>= 1) t = fmaxf(t, __shfl_xor_sync(0xffffffffu, t, o));
        if (tid == 0) red[32] = t;
    }
    __syncthreads();
    mx = red[32];
    __syncthreads();

    float sum = 0.f;
    for (int k = tid; k < LLAB; k += 128) {
        float e = expf(buf[k] - mx);
        buf[k] = e;
        sum += e;
    }
    for (int o = 16; o; o >>= 1) sum += __shfl_xor_sync(0xffffffffu, sum, o);
    if ((tid & 31) == 0) red[tid >> 5] = sum;
    __syncthreads();
    if (tid < 32) {
        float t = (tid < 4) ? red[tid] : 0.f;
        for (int o = 16; o; o >>= 1) t += __shfl_xor_sync(0xffffffffu, t, o);
        if (tid == 0) red[32] = t;
    }
    __syncthreads();
    float inv = 1.f / red[32];

    for (int k = tid; k < LLAB; k += 128) {
        bool kb1 = (k < NN1), kb3 = (k >= NN1 + NN2);
        bool Z = (qb1 && kb3) || (qb3 && kb1);
        row[k] = Z ? 0.f : buf[k] * inv;
    }
}

// ---------------- pooling softmax over S with pad mask ----------------
__global__ void pool_softmax(float* __restrict__ aw, const int* __restrict__ tok)
{
    const int l = blockIdx.x, b = blockIdx.y;
    float* row = aw + ((long)b * LLAB + l) * SSEQ;
    const int* t = tok + (long)b * SSEQ;

    __shared__ float buf[SSEQ];
    __shared__ float red[33];
    const int tid = threadIdx.x;   // 256 threads

    float mx = -INFINITY;
    for (int s = tid; s < SSEQ; s += 256) {
        int tv = t[s];
        bool bad = (tv == 0) || (tv == 101) || (tv == 102);
        float v = row[s] + (bad ? -INFINITY : 0.f);
        buf[s] = v;
        mx = fmaxf(mx, v);
    }
    for (int o = 16; o; o >>= 1) mx = fmaxf(mx, __shfl_xor_sync(0xffffffffu, mx, o));
    if ((tid & 31) == 0) red[tid >> 5] = mx;
    __syncthreads();
    if (tid < 32) {
        float v = (tid < 8) ? red[tid] : -INFINITY;
        for (int o = 16; o; o >>= 1) v = fmaxf(v, __shfl_xor_sync(0xffffffffu, v, o));
        if (tid == 0) red[32] = v;
    }
    __syncthreads();
    mx = red[32];
    __syncthreads();

    float sum = 0.f;
    for (int s = tid; s < SSEQ; s += 256) {
        float e = expf(buf[s] - mx);
        buf[s] = e;
        sum += e;
    }
    for (int o = 16; o; o >>= 1) sum += __shfl_xor_sync(0xffffffffu, sum, o);
    if ((tid & 31) == 0) red[tid >> 5] = sum;
    __syncthreads();
    if (tid < 32) {
        float v = (tid < 8) ? red[tid] : 0.f;
        for (int o = 16; o; o >>= 1) v += __shfl_xor_sync(0xffffffffu, v, o);
        if (tid == 0) red[32] = v;
    }
    __syncthreads();
    float inv = 1.f / red[32];

    for (int s = tid; s < SSEQ; s += 256) row[s] = buf[s] * inv;
}

// ---------------- final split-K reduce + sigmoid ----------------
__global__ void final_reduce(const float* __restrict__ part,
                             const float* __restrict__ bout,
                             float* __restrict__ out)
{
    int i = blockIdx.x * blockDim.x + threadIdx.x;  // over B*L
    if (i >= BBAT * LLAB) return;
    int l = i % LLAB;
    float s = bout[l];
    #pragma unroll
    for (int z = 0; z < NSPLIT; z++) s += part[z * (BBAT * LLAB) + i];
    out[i] = 1.f / (1.f + expf(-s));
}

// ---------------- host orchestration ----------------
extern "C" void kernel_launch(void* const* d_in, const int* in_sizes, int n_in,
                              void* d_out, int out_size)
{
    const int*   inputs      = (const int*)  d_in[0];
    const float* text_hidden = (const float*)d_in[1];
    const float* label_feat  = (const float*)d_in[2];
    const int*   amask       = (const int*)  d_in[3];
    const float* Wt   = (const float*)d_in[4];
    const float* bt   = (const float*)d_in[5];
    const float* Wl   = (const float*)d_in[6];
    const float* bl   = (const float*)d_in[7];
    const float* WK   = (const float*)d_in[8];
    const float* WQ   = (const float*)d_in[9];
    const float* WV   = (const float*)d_in[10];
    const float* PA   = (const float*)d_in[11];
    const float* PM   = (const float*)d_in[12];
    const float* WA   = (const float*)d_in[13];
    const float* Wout = (const float*)d_in[14];
    const float* bout = (const float*)d_in[15];
    float* out = (float*)d_out;

    float *te, *le, *Kb, *paq, *pmv, *sc, *mm, *aw, *feat, *part, *wqe, *wve;
    cudaGetSymbolAddress((void**)&te,   g_text_enc);
    cudaGetSymbolAddress((void**)&le,   g_le);
    cudaGetSymbolAddress((void**)&Kb,   g_Kb);
    cudaGetSymbolAddress((void**)&paq,  g_PAQ);
    cudaGetSymbolAddress((void**)&pmv,  g_PMV);
    cudaGetSymbolAddress((void**)&sc,   g_Sc);
    cudaGetSymbolAddress((void**)&mm,   g_M);
    cudaGetSymbolAddress((void**)&aw,   g_aw);
    cudaGetSymbolAddress((void**)&feat, g_feat);
    cudaGetSymbolAddress((void**)&part, g_part);
    cudaGetSymbolAddress((void**)&wqe,  g_WQe);
    cudaGetSymbolAddress((void**)&wve,  g_WVe);

    const float scale = 1.f / sqrtf((float)DHH);

    // effective weights (tiny)
    prep_eff<<<dim3(24, 2), 256>>>(WQ, WV, PA, PM, wqe, wve);

    // text_enc = tanh(text_hidden @ Wt^T + bt)   [16384, 256]
    sgemm128<1, false><<<dim3(cdiv(HIDC, 128), cdiv(BBAT * SSEQ, 128), 1), 256>>>(
        text_hidden, Wt, bt, te,
        BBAT * SSEQ, HIDC, DBERT, DBERT, DBERT, HIDC, 0, 0, 0);

    // le = label_feat @ Wl^T + bl   [600, 256]
    gemm_g<64, 64, 16, 4, 4, 0, false><<<dim3(cdiv(HIDC, 64), cdiv(LLAB, 64), 1), 256>>>(
        label_feat, Wl, bl, nullptr, le,
        LLAB, HIDC, DBERT, DBERT, DBERT, HIDC, 0, 0, 0, 1.f);

    for (int layer = 0; layer < 2; layer++) {
        // K / PAQ / PMV for all 3 relation types, one launch
        proj_fused<<<dim3(cdiv(HIDC, 64), cdiv(NN3, 64), 9), 256>>>(
            le, WK, wqe, wve, Kb, paq, pmv);

        // Sc[h,q,k] = scale * sum_d PAQ[q,h*32+d] * K[k,h*32+d]  (batched over h)
        gemm_g<64, 64, 16, 4, 4, 0, false><<<dim3(cdiv(LLAB, 64), cdiv(LLAB, 64), NHEAD), 256>>>(
            paq, Kb, nullptr, nullptr, sc,
            LLAB, LLAB, DHH, HIDC, HIDC, LLAB,
            DHH, DHH, (long)LLAB * LLAB, scale);

        attn_softmax<<<dim3(LLAB, NHEAD), 128>>>(sc, amask);

        // M[q, h*32+e] = sum_k Watt[h,q,k] * PMV[k, h*32+e]  (batched over h)
        gemm_g<64, 32, 16, 4, 2, 0, true><<<dim3(1, cdiv(LLAB, 64), NHEAD), 256>>>(
            sc, pmv, nullptr, nullptr, mm,
            LLAB, DHH, LLAB, LLAB, HIDC, HIDC,
            (long)LLAB * LLAB, DHH, DHH, 1.f);

        // le = tanh(per_type(M, WA)) + le, one launch
        wa_fused<<<dim3(cdiv(HIDC, 64), cdiv(NN3, 64), 3), 256>>>(mm, WA, le);
    }

    // aw[b,l,s] = sum_e le[l,e] * text_enc[b,s,e]   (batched over b)
    sgemm128<0, false><<<dim3(cdiv(SSEQ, 128), cdiv(LLAB, 128), BBAT), 256>>>(
        le, te, nullptr, aw,
        LLAB, SSEQ, HIDC, HIDC, HIDC, SSEQ,
        0, (long)SSEQ * HIDC, (long)LLAB * SSEQ);

    pool_softmax<<<dim3(LLAB, BBAT), 256>>>(aw, inputs);

    // features[b,l,e] = sum_s aw[b,l,s] * text_enc[b,s,e]   (batched over b)
    sgemm128<0, true><<<dim3(cdiv(HIDC, 128), cdiv(LLAB, 128), BBAT), 256>>>(
        aw, te, nullptr, feat,
        LLAB, HIDC, SSEQ, SSEQ, HIDC, HIDC,
        (long)LLAB * SSEQ, (long)SSEQ * HIDC, (long)LLAB * HIDC);

    // final GEMM, split-K: part[z][b][l] = sum_{k in split z} feat[b,k]*Wout[l,k]
    {
        const int KS = (LLAB * HIDC) / NSPLIT;   // 2400
        gemm_g<32, 128, 16, 4, 4, 0, false><<<dim3(cdiv(LLAB, 128), 1, NSPLIT), 256>>>(
            feat, Wout, nullptr, nullptr, part,
            BBAT, LLAB, KS,
            LLAB * HIDC, LLAB * HIDC, LLAB,
            (long)KS, (long)KS, (long)BBAT * LLAB, 1.f);
    }

    final_reduce<<<cdiv(BBAT * LLAB, 256), 256>>>(part, bout, out);
}

// round 4
// speedup vs baseline: 2.8734x; 1.5800x over previous
#include <cuda_runtime.h>
#include <math.h>
#include <stdint.h>

// ---------------- problem constants ----------------
#define HIDC  256
#define NHEAD 8
#define NN1   60
#define NN2   240
#define NN3   300
#define LLAB  600           // N1+N2+N3
#define DHH   32            // HID/H
#define BBAT  32
#define SSEQ  512
#define DBERT 768
#define NSPLIT 64           // split-K factor for final GEMM

// ---------------- device scratch ----------------
__device__ float g_text_enc[BBAT * SSEQ * HIDC];
__device__ float g_le      [LLAB * HIDC];
__device__ float g_Kb      [LLAB * HIDC];
__device__ float g_PAQ     [LLAB * HIDC];
__device__ float g_PMV     [LLAB * HIDC];
__device__ float g_Sc      [NHEAD * LLAB * LLAB];
__device__ float g_M       [LLAB * HIDC];
__device__ float g_aw      [BBAT * LLAB * SSEQ];
__device__ float g_feat    [BBAT * LLAB * HIDC];
__device__ float g_part    [NSPLIT * BBAT * LLAB];
__device__ float g_WQe     [3 * HIDC * HIDC];
__device__ float g_WVe     [3 * HIDC * HIDC];

static inline int cdiv(int a, int b) { return (a + b - 1) / b; }

// =====================================================================
// tf32 helpers
// =====================================================================
__device__ __forceinline__ uint32_t f2tf(float x) {
    uint32_t r;
    asm("cvt.rna.tf32.f32 %0, %1;" : "=r"(r) : "f"(x));
    return r;
}

__device__ __forceinline__ void mma_tf32(float* c, const uint32_t* a, const uint32_t* b) {
    asm("mma.sync.aligned.m16n8k8.row.col.f32.tf32.tf32.f32 "
        "{%0,%1,%2,%3}, {%4,%5,%6,%7}, {%8,%9}, {%0,%1,%2,%3};"
        : "+f"(c[0]), "+f"(c[1]), "+f"(c[2]), "+f"(c[3])
        : "r"(a[0]), "r"(a[1]), "r"(a[2]), "r"(a[3]), "r"(b[0]), "r"(b[1]));
}

// =====================================================================
// tf32 tensor-core GEMM (device body)
// MODE 0: Y = acc (+bias[n] if bias) ; MODE 1: Y = tanh(acc + bias[n])
// MODE 2: Y = tanh(acc) + res[m,n]
// TRANS_W=false: Y[m,n] = sum_k X[m,k]*W[n,k]   (W row-major [N,K])
// TRANS_W=true : Y[m,n] = sum_k X[m,k]*W[k,n]   (W row-major [K,N])
// Requires K % BK == 0, K % 4 == 0, N % 4 == 0 (for TRANS_W load vec)
// =====================================================================
template<int BM, int BN, int BK, int WM, int WN, int MODE, bool TRANS_W>
__device__ __forceinline__ void tgemm_dev(
    const float* __restrict__ X, const float* __restrict__ W,
    const float* __restrict__ bias, const float* __restrict__ res,
    float* __restrict__ Y,
    int M, int N, int K, int ldx, int ldw, int ldy)
{
    constexpr int NWARP = (BM / WM) * (BN / WN);
    constexpr int NTHR  = NWARP * 32;
    constexpr int LDA   = BM + 8;   // stride mod 32 == 8 -> conflict-free frag reads
    constexpr int LDB   = BN + 8;
    constexpr int MI = WM / 16, NI = WN / 8;

    __shared__ uint32_t As[BK][LDA];
    __shared__ uint32_t Bs[BK][LDB];

    const int m0 = blockIdx.y * BM, n0 = blockIdx.x * BN;
    const int tid  = threadIdx.x;
    const int lane = tid & 31, wid = tid >> 5;
    const int wN = wid % (BN / WN), wM = wid / (BN / WN);
    const int g = lane >> 2, tg = lane & 3;

    float acc[MI][NI][4];
    #pragma unroll
    for (int i = 0; i < MI; i++)
        #pragma unroll
        for (int j = 0; j < NI; j++)
            #pragma unroll
            for (int r = 0; r < 4; r++) acc[i][j][r] = 0.f;

    for (int k0 = 0; k0 < K; k0 += BK) {
        // ---- load A tile: X[M,K] -> As[k][m] (transpose), float4 along k
        for (int i = tid; i < BM * (BK / 4); i += NTHR) {
            int m = i / (BK / 4), kq = (i % (BK / 4)) * 4;
            int gm = m0 + m;
            float4 v = make_float4(0.f, 0.f, 0.f, 0.f);
            if (gm < M) v = *(const float4*)(X + (long)gm * ldx + k0 + kq);
            As[kq + 0][m] = f2tf(v.x);
            As[kq + 1][m] = f2tf(v.y);
            As[kq + 2][m] = f2tf(v.z);
            As[kq + 3][m] = f2tf(v.w);
        }
        // ---- load B tile -> Bs[k][n]
        if (!TRANS_W) {
            for (int i = tid; i < BN * (BK / 4); i += NTHR) {
                int n = i / (BK / 4), kq = (i % (BK / 4)) * 4;
                int gn = n0 + n;
                float4 v = make_float4(0.f, 0.f, 0.f, 0.f);
                if (gn < N) v = *(const float4*)(W + (long)gn * ldw + k0 + kq);
                Bs[kq + 0][n] = f2tf(v.x);
                Bs[kq + 1][n] = f2tf(v.y);
                Bs[kq + 2][n] = f2tf(v.z);
                Bs[kq + 3][n] = f2tf(v.w);
            }
        } else {
            for (int i = tid; i < BK * (BN / 4); i += NTHR) {
                int k = i / (BN / 4), nq = (i % (BN / 4)) * 4;
                int gn = n0 + nq;
                float4 v = make_float4(0.f, 0.f, 0.f, 0.f);
                if (gn < N) v = *(const float4*)(W + (long)(k0 + k) * ldw + gn);
                Bs[k][nq + 0] = f2tf(v.x);
                Bs[k][nq + 1] = f2tf(v.y);
                Bs[k][nq + 2] = f2tf(v.z);
                Bs[k][nq + 3] = f2tf(v.w);
            }
        }
        __syncthreads();

        #pragma unroll
        for (int kk = 0; kk < BK; kk += 8) {
            uint32_t a[MI][4], b[NI][2];
            #pragma unroll
            for (int mi = 0; mi < MI; mi++) {
                int mr = wM * WM + mi * 16;
                a[mi][0] = As[kk + tg][mr + g];
                a[mi][1] = As[kk + tg][mr + g + 8];
                a[mi][2] = As[kk + tg + 4][mr + g];
                a[mi][3] = As[kk + tg + 4][mr + g + 8];
            }
            #pragma unroll
            for (int ni = 0; ni < NI; ni++) {
                int nc = wN * WN + ni * 8;
                b[ni][0] = Bs[kk + tg][nc + g];
                b[ni][1] = Bs[kk + tg + 4][nc + g];
            }
            #pragma unroll
            for (int mi = 0; mi < MI; mi++)
                #pragma unroll
                for (int ni = 0; ni < NI; ni++)
                    mma_tf32(acc[mi][ni], a[mi], b[ni]);
        }
        __syncthreads();
    }

    // ---- epilogue
    #pragma unroll
    for (int mi = 0; mi < MI; mi++) {
        #pragma unroll
        for (int ni = 0; ni < NI; ni++) {
            int mr = m0 + wM * WM + mi * 16 + g;
            int nc = n0 + wN * WN + ni * 8 + 2 * tg;
            #pragma unroll
            for (int r = 0; r < 4; r++) {
                int m = mr + (r >> 1) * 8;
                int n = nc + (r & 1);
                if (m >= M || n >= N) continue;
                float v = acc[mi][ni][r];
                if (MODE == 0)      { if (bias) v += bias[n]; }
                else if (MODE == 1) { v = tanhf(v + bias[n]); }
                else if (MODE == 2) { v = tanhf(v) + res[(long)m * ldy + n]; }
                Y[(long)m * ldy + n] = v;
            }
        }
    }
}

// batched global wrapper
template<int BM, int BN, int BK, int WM, int WN, int MODE, bool TRANS_W>
__global__ void tgemm_g(const float* __restrict__ Xg, const float* __restrict__ Wg,
                        const float* __restrict__ bias, float* __restrict__ Yg,
                        int M, int N, int K, int ldx, int ldw, int ldy,
                        long bsx, long bsw, long bsy)
{
    int bz = blockIdx.z;
    tgemm_dev<BM, BN, BK, WM, WN, MODE, TRANS_W>(
        Xg + bz * bsx, Wg + bz * bsw, bias, nullptr, Yg + bz * bsy,
        M, N, K, ldx, ldw, ldy);
}

// =====================================================================
// fp32 64/32-tile GEMM (kept for the small K=32 / N=32 attention mats)
// =====================================================================
template<int BM, int BN, int BK, int TM, int TN, int MODE, bool TRANS_W>
__device__ __forceinline__ void gemm_dev(
    const float* __restrict__ X, const float* __restrict__ W,
    const float* __restrict__ bias, const float* __restrict__ res,
    float* __restrict__ Y,
    int M, int N, int K, int ldx, int ldw, int ldy, float alpha)
{
    constexpr int NT = (BM / TM) * (BN / TN);
    __shared__ float Xs[BK][BM + 4];
    __shared__ float Ws[BK][BN + 4];

    int m0 = blockIdx.y * BM, n0 = blockIdx.x * BN;
    int tid = threadIdx.x;
    int tx = tid % (BN / TN), ty = tid / (BN / TN);

    float acc[TM][TN];
    #pragma unroll
    for (int i = 0; i < TM; i++)
        #pragma unroll
        for (int j = 0; j < TN; j++) acc[i][j] = 0.f;

    for (int k0 = 0; k0 < K; k0 += BK) {
        for (int i = tid; i < BM * BK; i += NT) {
            int k = i % BK, m = i / BK;
            int gm = m0 + m, gk = k0 + k;
            Xs[k][m] = (gm < M && gk < K) ? X[(long)gm * ldx + gk] : 0.f;
        }
        if (!TRANS_W) {
            for (int i = tid; i < BN * BK; i += NT) {
                int k = i % BK, n = i / BK;
                int gn = n0 + n, gk = k0 + k;
                Ws[k][n] = (gn < N && gk < K) ? W[(long)gn * ldw + gk] : 0.f;
            }
        } else {
            for (int i = tid; i < BK * BN; i += NT) {
                int n = i % BN, k = i / BN;
                int gn = n0 + n, gk = k0 + k;
                Ws[k][n] = (gn < N && gk < K) ? W[(long)gk * ldw + gn] : 0.f;
            }
        }
        __syncthreads();
        #pragma unroll
        for (int k = 0; k < BK; k++) {
            float a[TM], b[TN];
            #pragma unroll
            for (int i = 0; i < TM; i++) a[i] = Xs[k][ty * TM + i];
            #pragma unroll
            for (int j = 0; j < TN; j++) b[j] = Ws[k][tx * TN + j];
            #pragma unroll
            for (int i = 0; i < TM; i++)
                #pragma unroll
                for (int j = 0; j < TN; j++) acc[i][j] += a[i] * b[j];
        }
        __syncthreads();
    }

    #pragma unroll
    for (int i = 0; i < TM; i++) {
        int m = m0 + ty * TM + i;
        if (m >= M) continue;
        #pragma unroll
        for (int j = 0; j < TN; j++) {
            int n = n0 + tx * TN + j;
            if (n >= N) continue;
            float v = acc[i][j] * alpha;
            if (MODE == 0)      { if (bias) v += bias[n]; }
            else if (MODE == 2) { v = tanhf(v) + res[(long)m * ldy + n]; }
            Y[(long)m * ldy + n] = v;
        }
    }
}

template<int BM, int BN, int BK, int TM, int TN, int MODE, bool TRANS_W>
__global__ void gemm_g(const float* __restrict__ X, const float* __restrict__ W,
                       const float* __restrict__ bias, const float* __restrict__ res,
                       float* __restrict__ Y,
                       int M, int N, int K, int ldx, int ldw, int ldy,
                       long bsx, long bsw, long bsy, float alpha)
{
    int bz = blockIdx.z;
    gemm_dev<BM, BN, BK, TM, TN, MODE, TRANS_W>(
        X + bz * bsx, W + bz * bsw, bias,
        (MODE == 2) ? (res + bz * bsy) : res,
        Y + bz * bsy, M, N, K, ldx, ldw, ldy, alpha);
}

// =====================================================================
// Effective weights: WQe[t][h*32+e][c] = sum_d PA[e][d] * WQ[t][h*32+d][c]
// =====================================================================
__global__ void prep_eff(const float* __restrict__ WQ, const float* __restrict__ WV,
                         const float* __restrict__ PA, const float* __restrict__ PM,
                         float* __restrict__ WQe, float* __restrict__ WVe)
{
    int t = blockIdx.x >> 3, h = blockIdx.x & 7;
    const float* W = (blockIdx.y == 0 ? WQ : WV) + (long)t * HIDC * HIDC + (long)h * DHH * HIDC;
    const float* P = (blockIdx.y == 0 ? PA : PM);
    float* O = (blockIdx.y == 0 ? WQe : WVe) + (long)t * HIDC * HIDC + (long)h * DHH * HIDC;

    __shared__ float Ps[DHH][DHH];
    int tid = threadIdx.x;
    for (int i = tid; i < DHH * DHH; i += 256) Ps[i / DHH][i % DHH] = P[i];
    __syncthreads();

    int c = tid;
    float w[DHH];
    #pragma unroll
    for (int d = 0; d < DHH; d++) w[d] = W[(long)d * HIDC + c];
    #pragma unroll
    for (int e = 0; e < DHH; e++) {
        float s = 0.f;
        #pragma unroll
        for (int d = 0; d < DHH; d++) s += Ps[e][d] * w[d];
        O[(long)e * HIDC + c] = s;
    }
}

// =====================================================================
// Fused per-type projections, tf32. grid (4, 5, 9), 128 threads.
// =====================================================================
__global__ void proj_fused(const float* __restrict__ le,
                           const float* __restrict__ WK,
                           const float* __restrict__ WQe,
                           const float* __restrict__ WVe,
                           float* __restrict__ Kb, float* __restrict__ PAQ,
                           float* __restrict__ PMV)
{
    int z = blockIdx.z;
    int t = z % 3, which = z / 3;
    int s0 = (t == 0) ? 0 : (t == 1 ? NN1 : NN1 + NN2);
    int cnt = (t == 0) ? NN1 : (t == 1 ? NN2 : NN3);
    if ((int)blockIdx.y * 64 >= cnt) return;
    const float* W = (which == 0 ? WK : (which == 1 ? WQe : WVe)) + (long)t * HIDC * HIDC;
    float* Y = (which == 0 ? Kb : (which == 1 ? PAQ : PMV)) + (long)s0 * HIDC;
    tgemm_dev<64, 64, 32, 32, 32, 0, false>(
        le + (long)s0 * HIDC, W, nullptr, nullptr, Y,
        cnt, HIDC, HIDC, HIDC, HIDC, HIDC);
}

// Fused WA epilogue: le = tanh(per_type(M, WA)) + le. grid (4, 5, 3), 128 thr.
__global__ void wa_fused(const float* __restrict__ Mm, const float* __restrict__ WA,
                         float* __restrict__ le)
{
    int t = blockIdx.z;
    int s0 = (t == 0) ? 0 : (t == 1 ? NN1 : NN1 + NN2);
    int cnt = (t == 0) ? NN1 : (t == 1 ? NN2 : NN3);
    if ((int)blockIdx.y * 64 >= cnt) return;
    tgemm_dev<64, 64, 32, 32, 32, 2, false>(
        Mm + (long)s0 * HIDC, WA + (long)t * HIDC * HIDC, nullptr,
        le + (long)s0 * HIDC, le + (long)s0 * HIDC,
        cnt, HIDC, HIDC, HIDC, HIDC, HIDC);
}

// =====================================================================
// Attention softmax (zero-block + additive mask), in place
// =====================================================================
__global__ void attn_softmax(float* __restrict__ Sc, const int* __restrict__ amask)
{
    const int q = blockIdx.x, h = blockIdx.y;
    float* row = Sc + ((long)h * LLAB + q) * LLAB;
    const int* mrow = amask + (long)q * LLAB;

    __shared__ float buf[LLAB];
    __shared__ float red[33];
    const int tid = threadIdx.x;          // 128
    const bool qb1 = (q < NN1), qb3 = (q >= NN1 + NN2);

    float mx = -INFINITY;
    for (int k = tid; k < LLAB; k += 128) {
        bool kb1 = (k < NN1), kb3 = (k >= NN1 + NN2);
        bool Z = (qb1 && kb3) || (qb3 && kb1);
        float mk = (mrow[k] == 0) ? -INFINITY : 0.f;
        float v = (Z ? 0.f : row[k]) + mk;
        buf[k] = v;
        mx = fmaxf(mx, v);
    }
    for (int o = 16; o; o >>= 1) mx = fmaxf(mx, __shfl_xor_sync(0xffffffffu, mx, o));
    if ((tid & 31) == 0) red[tid >> 5] = mx;
    __syncthreads();
    if (tid < 32) {
        float t = (tid < 4) ? red[tid] : -INFINITY;
        for (int o = 16; o; o >>= 1) t = fmaxf(t, __shfl_xor_sync(0xffffffffu, t, o));
        if (tid == 0) red[32] = t;
    }
    __syncthreads();
    mx = red[32];
    __syncthreads();

    float sum = 0.f;
    for (int k = tid; k < LLAB; k += 128) {
        float e = expf(buf[k] - mx);
        buf[k] = e;
        sum += e;
    }
    for (int o = 16; o; o >>= 1) sum += __shfl_xor_sync(0xffffffffu, sum, o);
    if ((tid & 31) == 0) red[tid >> 5] = sum;
    __syncthreads();
    if (tid < 32) {
        float t = (tid < 4) ? red[tid] : 0.f;
        for (int o = 16; o; o >>= 1) t += __shfl_xor_sync(0xffffffffu, t, o);
        if (tid == 0) red[32] = t;
    }
    __syncthreads();
    float inv = 1.f / red[32];

    for (int k = tid; k < LLAB; k += 128) {
        bool kb1 = (k < NN1), kb3 = (k >= NN1 + NN2);
        bool Z = (qb1 && kb3) || (qb3 && kb1);
        row[k] = Z ? 0.f : buf[k] * inv;
    }
}

// ---------------- pooling softmax over S with pad mask ----------------
__global__ void pool_softmax(float* __restrict__ aw, const int* __restrict__ tok)
{
    const int l = blockIdx.x, b = blockIdx.y;
    float* row = aw + ((long)b * LLAB + l) * SSEQ;
    const int* t = tok + (long)b * SSEQ;

    __shared__ float buf[SSEQ];
    __shared__ float red[33];
    const int tid = threadIdx.x;   // 256

    float mx = -INFINITY;
    for (int s = tid; s < SSEQ; s += 256) {
        int tv = t[s];
        bool bad = (tv == 0) || (tv == 101) || (tv == 102);
        float v = row[s] + (bad ? -INFINITY : 0.f);
        buf[s] = v;
        mx = fmaxf(mx, v);
    }
    for (int o = 16; o; o >>= 1) mx = fmaxf(mx, __shfl_xor_sync(0xffffffffu, mx, o));
    if ((tid & 31) == 0) red[tid >> 5] = mx;
    __syncthreads();
    if (tid < 32) {
        float v = (tid < 8) ? red[tid] : -INFINITY;
        for (int o = 16; o; o >>= 1) v = fmaxf(v, __shfl_xor_sync(0xffffffffu, v, o));
        if (tid == 0) red[32] = v;
    }
    __syncthreads();
    mx = red[32];
    __syncthreads();

    float sum = 0.f;
    for (int s = tid; s < SSEQ; s += 256) {
        float e = expf(buf[s] - mx);
        buf[s] = e;
        sum += e;
    }
    for (int o = 16; o; o >>= 1) sum += __shfl_xor_sync(0xffffffffu, sum, o);
    if ((tid & 31) == 0) red[tid >> 5] = sum;
    __syncthreads();
    if (tid < 32) {
        float v = (tid < 8) ? red[tid] : 0.f;
        for (int o = 16; o; o >>= 1) v += __shfl_xor_sync(0xffffffffu, v, o);
        if (tid == 0) red[32] = v;
    }
    __syncthreads();
    float inv = 1.f / red[32];

    for (int s = tid; s < SSEQ; s += 256) row[s] = buf[s] * inv;
}

// ---------------- final split-K reduce + sigmoid ----------------
__global__ void final_reduce(const float* __restrict__ part,
                             const float* __restrict__ bout,
                             float* __restrict__ out)
{
    int i = blockIdx.x * blockDim.x + threadIdx.x;
    if (i >= BBAT * LLAB) return;
    int l = i % LLAB;
    float s = bout[l];
    #pragma unroll
    for (int z = 0; z < NSPLIT; z++) s += part[z * (BBAT * LLAB) + i];
    out[i] = 1.f / (1.f + expf(-s));
}

// ---------------- host orchestration ----------------
extern "C" void kernel_launch(void* const* d_in, const int* in_sizes, int n_in,
                              void* d_out, int out_size)
{
    const int*   inputs      = (const int*)  d_in[0];
    const float* text_hidden = (const float*)d_in[1];
    const float* label_feat  = (const float*)d_in[2];
    const int*   amask       = (const int*)  d_in[3];
    const float* Wt   = (const float*)d_in[4];
    const float* bt   = (const float*)d_in[5];
    const float* Wl   = (const float*)d_in[6];
    const float* bl   = (const float*)d_in[7];
    const float* WK   = (const float*)d_in[8];
    const float* WQ   = (const float*)d_in[9];
    const float* WV   = (const float*)d_in[10];
    const float* PA   = (const float*)d_in[11];
    const float* PM   = (const float*)d_in[12];
    const float* WA   = (const float*)d_in[13];
    const float* Wout = (const float*)d_in[14];
    const float* bout = (const float*)d_in[15];
    float* out = (float*)d_out;

    float *te, *le, *Kb, *paq, *pmv, *sc, *mm, *aw, *feat, *part, *wqe, *wve;
    cudaGetSymbolAddress((void**)&te,   g_text_enc);
    cudaGetSymbolAddress((void**)&le,   g_le);
    cudaGetSymbolAddress((void**)&Kb,   g_Kb);
    cudaGetSymbolAddress((void**)&paq,  g_PAQ);
    cudaGetSymbolAddress((void**)&pmv,  g_PMV);
    cudaGetSymbolAddress((void**)&sc,   g_Sc);
    cudaGetSymbolAddress((void**)&mm,   g_M);
    cudaGetSymbolAddress((void**)&aw,   g_aw);
    cudaGetSymbolAddress((void**)&feat, g_feat);
    cudaGetSymbolAddress((void**)&part, g_part);
    cudaGetSymbolAddress((void**)&wqe,  g_WQe);
    cudaGetSymbolAddress((void**)&wve,  g_WVe);

    const float scale = 1.f / sqrtf((float)DHH);

    // effective weights (tiny)
    prep_eff<<<dim3(24, 2), 256>>>(WQ, WV, PA, PM, wqe, wve);

    // text_enc = tanh(text_hidden @ Wt^T + bt)   [16384, 256] K=768  (tf32)
    tgemm_g<128, 128, 32, 64, 32, 1, false><<<dim3(cdiv(HIDC, 128), cdiv(BBAT * SSEQ, 128), 1), 256>>>(
        text_hidden, Wt, bt, te,
        BBAT * SSEQ, HIDC, DBERT, DBERT, DBERT, HIDC, 0, 0, 0);

    // le = label_feat @ Wl^T + bl   [600, 256] K=768  (fp32, tiny)
    gemm_g<64, 64, 16, 4, 4, 0, false><<<dim3(cdiv(HIDC, 64), cdiv(LLAB, 64), 1), 256>>>(
        label_feat, Wl, bl, nullptr, le,
        LLAB, HIDC, DBERT, DBERT, DBERT, HIDC, 0, 0, 0, 1.f);

    for (int layer = 0; layer < 2; layer++) {
        // K / PAQ / PMV for all 3 relation types, one tf32 launch
        proj_fused<<<dim3(cdiv(HIDC, 64), cdiv(NN3, 64), 9), 128>>>(
            le, WK, wqe, wve, Kb, paq, pmv);

        // Sc[h,q,k] = scale * PAQ[q,h*32:]·K[k,h*32:]  (K=32, fp32, batched h)
        gemm_g<64, 64, 16, 4, 4, 0, false><<<dim3(cdiv(LLAB, 64), cdiv(LLAB, 64), NHEAD), 256>>>(
            paq, Kb, nullptr, nullptr, sc,
            LLAB, LLAB, DHH, HIDC, HIDC, LLAB,
            DHH, DHH, (long)LLAB * LLAB, scale);

        attn_softmax<<<dim3(LLAB, NHEAD), 128>>>(sc, amask);

        // M[q, h*32+e] = sum_k Watt[h,q,k] * PMV[k, h*32+e]  (fp32, batched h)
        gemm_g<32, 32, 16, 2, 2, 0, true><<<dim3(1, cdiv(LLAB, 32), NHEAD), 256>>>(
            sc, pmv, nullptr, nullptr, mm,
            LLAB, DHH, LLAB, LLAB, HIDC, HIDC,
            (long)LLAB * LLAB, DHH, DHH, 1.f);

        // le = tanh(per_type(M, WA)) + le, one tf32 launch
        wa_fused<<<dim3(cdiv(HIDC, 64), cdiv(NN3, 64), 3), 128>>>(mm, WA, le);
    }

    // aw[b,l,s] = le[l,:]·te[b,s,:]   [600,512] K=256, batched over b (tf32)
    tgemm_g<128, 128, 32, 64, 32, 0, false><<<dim3(cdiv(SSEQ, 128), cdiv(LLAB, 128), BBAT), 256>>>(
        le, te, nullptr, aw,
        LLAB, SSEQ, HIDC, HIDC, HIDC, SSEQ,
        0, (long)SSEQ * HIDC, (long)LLAB * SSEQ);

    pool_softmax<<<dim3(LLAB, BBAT), 256>>>(aw, inputs);

    // features[b,l,e] = sum_s aw[b,l,s] * te[b,s,e]  [600,256] K=512 (tf32, NN)
    tgemm_g<128, 128, 32, 64, 32, 0, true><<<dim3(cdiv(HIDC, 128), cdiv(LLAB, 128), BBAT), 256>>>(
        aw, te, nullptr, feat,
        LLAB, HIDC, SSEQ, SSEQ, HIDC, HIDC,
        (long)LLAB * SSEQ, (long)SSEQ * HIDC, (long)LLAB * HIDC);

    // final GEMM, split-K 64: part[z][b][l]  M=32, N=600, K=2400/slice (tf32)
    {
        const int KS = (LLAB * HIDC) / NSPLIT;   // 2400
        tgemm_g<32, 128, 32, 16, 32, 0, false><<<dim3(cdiv(LLAB, 128), 1, NSPLIT), 256>>>(
            feat, Wout, nullptr, part,
            BBAT, LLAB, KS,
            LLAB * HIDC, LLAB * HIDC, LLAB,
            (long)KS, (long)KS, (long)BBAT * LLAB);
    }

    final_reduce<<<cdiv(BBAT * LLAB, 256), 256>>>(part, bout, out);
}

// round 5
// speedup vs baseline: 5.7084x; 1.9867x over previous
#include <cuda_runtime.h>
#include <math.h>
#include <stdint.h>

// ---------------- problem constants ----------------
#define HIDC  256
#define NHEAD 8
#define NN1   60
#define NN2   240
#define NN3   300
#define LLAB  600
#define DHH   32
#define BBAT  32
#define SSEQ  512
#define DBERT 768
#define NSPLIT 64

#define ATTN_SMEM (32 * 601 * 4)

// ---------------- device scratch ----------------
__device__ float g_text_enc[BBAT * SSEQ * HIDC];
__device__ float g_le      [LLAB * HIDC];
__device__ float g_Kb      [LLAB * HIDC];
__device__ float g_PAQ     [LLAB * HIDC];
__device__ float g_PMV     [LLAB * HIDC];
__device__ float g_M       [LLAB * HIDC];
__device__ float g_aw      [BBAT * LLAB * SSEQ];
__device__ float g_feat    [BBAT * LLAB * HIDC];
__device__ float g_part    [NSPLIT * BBAT * LLAB];
__device__ float g_WQe     [3 * HIDC * HIDC];
__device__ float g_WVe     [3 * HIDC * HIDC];

static inline int cdiv(int a, int b) { return (a + b - 1) / b; }

// =====================================================================
// helpers
// =====================================================================
__device__ __forceinline__ uint32_t f2tf(float x) {
    uint32_t r;
    asm("cvt.rna.tf32.f32 %0, %1;" : "=r"(r) : "f"(x));
    return r;
}

__device__ __forceinline__ void mma_tf32(float* c, const uint32_t* a, const uint32_t* b) {
    asm("mma.sync.aligned.m16n8k8.row.col.f32.tf32.tf32.f32 "
        "{%0,%1,%2,%3}, {%4,%5,%6,%7}, {%8,%9}, {%0,%1,%2,%3};"
        : "+f"(c[0]), "+f"(c[1]), "+f"(c[2]), "+f"(c[3])
        : "r"(a[0]), "r"(a[1]), "r"(a[2]), "r"(a[3]), "r"(b[0]), "r"(b[1]));
}

__device__ __forceinline__ void cpa16(void* s, const void* g, bool v) {
    uint32_t sa = (uint32_t)__cvta_generic_to_shared(s);
    int sz = v ? 16 : 0;
    asm volatile("cp.async.cg.shared.global [%0], [%1], 16, %2;" :: "r"(sa), "l"(g), "r"(sz));
}
__device__ __forceinline__ void cp_commit() { asm volatile("cp.async.commit_group;"); }
__device__ __forceinline__ void cp_wait1()  { asm volatile("cp.async.wait_group 1;"); }
__device__ __forceinline__ void cp_wait0()  { asm volatile("cp.async.wait_group 0;"); }

// =====================================================================
// 2-stage cp.async pipelined tf32 GEMM (device body)
// MODE 0: Y = acc (+bias[n]) ; MODE 1: Y = tanh(acc+bias) ; MODE 2: Y = tanh(acc)+res
// TRANS_W=false: Y[m,n]=sum_k X[m,k]*W[n,k] ; true: W[k,n]
// Requires: K % 16 == 0, K % 4 == 0, N % 4 == 0, 16B-aligned rows
// =====================================================================
template<int BM, int BN, int BK, int WM, int WN, int MODE, bool TRANS_W>
__device__ __forceinline__ void tgemm_dev(
    const float* __restrict__ X, const float* __restrict__ W,
    const float* __restrict__ bias, const float* __restrict__ res,
    float* __restrict__ Y,
    int M, int N, int K, int ldx, int ldw, int ldy)
{
    constexpr int NWARP = (BM / WM) * (BN / WN);
    constexpr int NTHR  = NWARP * 32;
    constexpr int LDA   = BK + 4;                       // [m][k] stride
    constexpr int LDBN  = BK + 4;                       // NT: [n][k]
    constexpr int LDBT  = BN + 8;                       // TRANS: [k][n]
    constexpr int MI = WM / 16, NI = WN / 8;

    __shared__ float As[2][BM * LDA];
    __shared__ float Bs[2][TRANS_W ? (BK * LDBT) : (BN * LDBN)];

    const int m0 = blockIdx.y * BM, n0 = blockIdx.x * BN;
    const int tid  = threadIdx.x;
    const int lane = tid & 31, wid = tid >> 5;
    const int wN = wid % (BN / WN), wM = wid / (BN / WN);
    const int g = lane >> 2, tg = lane & 3;

    float acc[MI][NI][4];
    #pragma unroll
    for (int i = 0; i < MI; i++)
        #pragma unroll
        for (int j = 0; j < NI; j++)
            #pragma unroll
            for (int r = 0; r < 4; r++) acc[i][j][r] = 0.f;

    const int T = K / BK;

    auto load_tile = [&](int t, int st) {
        int k0 = t * BK;
        // A tile: BM rows x BK cols -> As[m][k]
        #pragma unroll
        for (int c = tid; c < BM * (BK / 4); c += NTHR) {
            int row = c >> 2, kq = (c & 3) * 4;
            bool v = (m0 + row) < M;
            int gr = v ? (m0 + row) : 0;
            cpa16(&As[st][row * LDA + kq], X + (long)gr * ldx + k0 + kq, v);
        }
        if (!TRANS_W) {
            #pragma unroll
            for (int c = tid; c < BN * (BK / 4); c += NTHR) {
                int row = c >> 2, kq = (c & 3) * 4;
                bool v = (n0 + row) < N;
                int gr = v ? (n0 + row) : 0;
                cpa16(&Bs[st][row * LDBN + kq], W + (long)gr * ldw + k0 + kq, v);
            }
        } else {
            #pragma unroll
            for (int c = tid; c < BK * (BN / 4); c += NTHR) {
                int k = c / (BN / 4), nq = (c % (BN / 4)) * 4;
                bool v = (n0 + nq) < N;
                int gc = v ? (n0 + nq) : 0;
                cpa16(&Bs[st][k * LDBT + nq], W + (long)(k0 + k) * ldw + gc, v);
            }
        }
    };

    load_tile(0, 0);
    cp_commit();

    for (int t = 0; t < T; t++) {
        int cur = t & 1;
        if (t + 1 < T) {
            load_tile(t + 1, cur ^ 1);
            cp_commit();
            cp_wait1();
        } else {
            cp_wait0();
        }
        __syncthreads();

        #pragma unroll
        for (int kk = 0; kk < BK; kk += 8) {
            uint32_t a[MI][4], b[NI][2];
            #pragma unroll
            for (int mi = 0; mi < MI; mi++) {
                int mr = wM * WM + mi * 16;
                a[mi][0] = f2tf(As[cur][(mr + g)     * LDA + kk + tg]);
                a[mi][1] = f2tf(As[cur][(mr + g + 8) * LDA + kk + tg]);
                a[mi][2] = f2tf(As[cur][(mr + g)     * LDA + kk + tg + 4]);
                a[mi][3] = f2tf(As[cur][(mr + g + 8) * LDA + kk + tg + 4]);
            }
            #pragma unroll
            for (int ni = 0; ni < NI; ni++) {
                int nc = wN * WN + ni * 8;
                if (!TRANS_W) {
                    b[ni][0] = f2tf(Bs[cur][(nc + g) * LDBN + kk + tg]);
                    b[ni][1] = f2tf(Bs[cur][(nc + g) * LDBN + kk + tg + 4]);
                } else {
                    b[ni][0] = f2tf(Bs[cur][(kk + tg)     * LDBT + nc + g]);
                    b[ni][1] = f2tf(Bs[cur][(kk + tg + 4) * LDBT + nc + g]);
                }
            }
            #pragma unroll
            for (int mi = 0; mi < MI; mi++)
                #pragma unroll
                for (int ni = 0; ni < NI; ni++)
                    mma_tf32(acc[mi][ni], a[mi], b[ni]);
        }
        __syncthreads();
    }

    #pragma unroll
    for (int mi = 0; mi < MI; mi++) {
        #pragma unroll
        for (int ni = 0; ni < NI; ni++) {
            int mr = m0 + wM * WM + mi * 16 + g;
            int nc = n0 + wN * WN + ni * 8 + 2 * tg;
            #pragma unroll
            for (int r = 0; r < 4; r++) {
                int m = mr + (r >> 1) * 8;
                int n = nc + (r & 1);
                if (m >= M || n >= N) continue;
                float v = acc[mi][ni][r];
                if (MODE == 0)      { if (bias) v += bias[n]; }
                else if (MODE == 1) { v = tanhf(v + bias[n]); }
                else if (MODE == 2) { v = tanhf(v) + res[(long)m * ldy + n]; }
                Y[(long)m * ldy + n] = v;
            }
        }
    }
}

// batched global wrapper
template<int BM, int BN, int BK, int WM, int WN, int MODE, bool TRANS_W>
__global__ void __launch_bounds__((BM / WM) * (BN / WN) * 32)
tgemm_g(const float* __restrict__ Xg, const float* __restrict__ Wg,
        const float* __restrict__ bias, float* __restrict__ Yg,
        int M, int N, int K, int ldx, int ldw, int ldy,
        long bsx, long bsw, long bsy)
{
    int bz = blockIdx.z;
    tgemm_dev<BM, BN, BK, WM, WN, MODE, TRANS_W>(
        Xg + bz * bsx, Wg + bz * bsw, bias, nullptr, Yg + bz * bsy,
        M, N, K, ldx, ldw, ldy);
}

// =====================================================================
// Effective weights: WQe[t][h*32+e][c] = sum_d PA[e][d] * WQ[t][h*32+d][c]
// =====================================================================
__global__ void prep_eff(const float* __restrict__ WQ, const float* __restrict__ WV,
                         const float* __restrict__ PA, const float* __restrict__ PM,
                         float* __restrict__ WQe, float* __restrict__ WVe)
{
    int t = blockIdx.x >> 3, h = blockIdx.x & 7;
    const float* W = (blockIdx.y == 0 ? WQ : WV) + (long)t * HIDC * HIDC + (long)h * DHH * HIDC;
    const float* P = (blockIdx.y == 0 ? PA : PM);
    float* O = (blockIdx.y == 0 ? WQe : WVe) + (long)t * HIDC * HIDC + (long)h * DHH * HIDC;

    __shared__ float Ps[DHH][DHH];
    int tid = threadIdx.x;
    for (int i = tid; i < DHH * DHH; i += 256) Ps[i / DHH][i % DHH] = P[i];
    __syncthreads();

    int c = tid;
    float w[DHH];
    #pragma unroll
    for (int d = 0; d < DHH; d++) w[d] = W[(long)d * HIDC + c];
    #pragma unroll
    for (int e = 0; e < DHH; e++) {
        float s = 0.f;
        #pragma unroll
        for (int d = 0; d < DHH; d++) s += Ps[e][d] * w[d];
        O[(long)e * HIDC + c] = s;
    }
}

// =====================================================================
// Fused per-type projections: grid (4, 5, 9), 128 threads
// =====================================================================
__global__ void __launch_bounds__(128)
proj_fused(const float* __restrict__ le,
           const float* __restrict__ WK,
           const float* __restrict__ WQe,
           const float* __restrict__ WVe,
           float* __restrict__ Kb, float* __restrict__ PAQ,
           float* __restrict__ PMV)
{
    int z = blockIdx.z;
    int t = z % 3, which = z / 3;
    int s0 = (t == 0) ? 0 : (t == 1 ? NN1 : NN1 + NN2);
    int cnt = (t == 0) ? NN1 : (t == 1 ? NN2 : NN3);
    if ((int)blockIdx.y * 64 >= cnt) return;
    const float* W = (which == 0 ? WK : (which == 1 ? WQe : WVe)) + (long)t * HIDC * HIDC;
    float* Y = (which == 0 ? Kb : (which == 1 ? PAQ : PMV)) + (long)s0 * HIDC;
    tgemm_dev<64, 64, 16, 32, 32, 0, false>(
        le + (long)s0 * HIDC, W, nullptr, nullptr, Y,
        cnt, HIDC, HIDC, HIDC, HIDC, HIDC);
}

// Fused WA epilogue: le = tanh(per_type(M, WA)) + le. grid (4, 5, 3), 128 thr
__global__ void __launch_bounds__(128)
wa_fused(const float* __restrict__ Mm, const float* __restrict__ WA,
         float* __restrict__ le)
{
    int t = blockIdx.z;
    int s0 = (t == 0) ? 0 : (t == 1 ? NN1 : NN1 + NN2);
    int cnt = (t == 0) ? NN1 : (t == 1 ? NN2 : NN3);
    if ((int)blockIdx.y * 64 >= cnt) return;
    tgemm_dev<64, 64, 16, 32, 32, 2, false>(
        Mm + (long)s0 * HIDC, WA + (long)t * HIDC * HIDC, nullptr,
        le + (long)s0 * HIDC, le + (long)s0 * HIDC,
        cnt, HIDC, HIDC, HIDC, HIDC, HIDC);
}

// =====================================================================
// Fused HGT attention: scores + masked softmax + P@PMV in one kernel.
// grid (19, 8), 256 threads, dynamic smem Ss[32][601].
// Mout[q, h*32+e] = sum_k softmax_sem(q,k) * PMV[k, h*32+e]
// =====================================================================
__global__ void __launch_bounds__(256)
attn_fused(const float* __restrict__ paq, const float* __restrict__ Kb,
           const float* __restrict__ pmv, const int* __restrict__ amask,
           float* __restrict__ Mout)
{
    extern __shared__ float Ss[];        // [32][601]
    __shared__ float invs[32];
    const float scale = 0.17677669529663687f;   // 1/sqrt(32)

    const int qt = blockIdx.x, h = blockIdx.y;
    const int q0 = qt * 32, hd = h * DHH;
    const int tid = threadIdx.x, lane = tid & 31, wid = tid >> 5;

    // ---- phase 1: raw scores. lane = q row; warp owns k-stripe of 75.
    {
        int gq = q0 + lane;
        int qc = (gq < LLAB) ? gq : (LLAB - 1);
        float qreg[DHH];
        #pragma unroll
        for (int d = 0; d < DHH; d++) qreg[d] = paq[(long)qc * HIDC + hd + d];

        int kend = wid * 75 + 75;
        for (int k = wid * 75; k < kend; k++) {
            float kv = Kb[(long)k * HIDC + hd + lane];
            float s = 0.f;
            #pragma unroll
            for (int d = 0; d < DHH; d++)
                s = fmaf(qreg[d], __shfl_sync(0xffffffffu, kv, d), s);
            Ss[lane * 601 + k] = s;
        }
    }
    __syncthreads();

    // ---- phase 2: masked softmax per row (warp handles 4 rows)
    #pragma unroll
    for (int rr = 0; rr < 4; rr++) {
        int q = wid * 4 + rr;
        int gq = q0 + q;
        if (gq >= LLAB) continue;
        bool qb1 = (gq < NN1), qb3 = (gq >= NN1 + NN2);

        float mx = -INFINITY;
        for (int k = lane; k < LLAB; k += 32) {
            bool kb1 = (k < NN1), kb3 = (k >= NN1 + NN2);
            bool Z = (qb1 && kb3) || (qb3 && kb1);
            float mk = (amask[(long)gq * LLAB + k] == 0) ? -INFINITY : 0.f;
            float v = (Z ? 0.f : Ss[q * 601 + k] * scale) + mk;
            Ss[q * 601 + k] = v;
            mx = fmaxf(mx, v);
        }
        #pragma unroll
        for (int o = 16; o; o >>= 1) mx = fmaxf(mx, __shfl_xor_sync(0xffffffffu, mx, o));

        float sum = 0.f;
        for (int k = lane; k < LLAB; k += 32) {
            bool kb1 = (k < NN1), kb3 = (k >= NN1 + NN2);
            bool Z = (qb1 && kb3) || (qb3 && kb1);
            float e = expf(Ss[q * 601 + k] - mx);
            sum += e;
            Ss[q * 601 + k] = Z ? 0.f : e;
        }
        #pragma unroll
        for (int o = 16; o; o >>= 1) sum += __shfl_xor_sync(0xffffffffu, sum, o);
        if (lane == 0) invs[q] = 1.f / sum;
    }
    __syncthreads();

    // ---- phase 3: M[q, hd+e] = inv[q] * sum_k P[q,k] * PMV[k, hd+e]
    {
        float acc0 = 0.f, acc1 = 0.f, acc2 = 0.f, acc3 = 0.f;
        const int qb = wid * 4;
        for (int k = 0; k < LLAB; k += 2) {
            float pv0 = pmv[(long)k * HIDC + hd + lane];
            float pv1 = pmv[(long)(k + 1) * HIDC + hd + lane];
            acc0 = fmaf(Ss[(qb + 0) * 601 + k], pv0, acc0);
            acc1 = fmaf(Ss[(qb + 1) * 601 + k], pv0, acc1);
            acc2 = fmaf(Ss[(qb + 2) * 601 + k], pv0, acc2);
            acc3 = fmaf(Ss[(qb + 3) * 601 + k], pv0, acc3);
            acc0 = fmaf(Ss[(qb + 0) * 601 + k + 1], pv1, acc0);
            acc1 = fmaf(Ss[(qb + 1) * 601 + k + 1], pv1, acc1);
            acc2 = fmaf(Ss[(qb + 2) * 601 + k + 1], pv1, acc2);
            acc3 = fmaf(Ss[(qb + 3) * 601 + k + 1], pv1, acc3);
        }
        float accs[4] = {acc0, acc1, acc2, acc3};
        #pragma unroll
        for (int rr = 0; rr < 4; rr++) {
            int gq = q0 + qb + rr;
            if (gq < LLAB)
                Mout[(long)gq * HIDC + hd + lane] = accs[rr] * invs[qb + rr];
        }
    }
}

// ---------------- pooling softmax over S with pad mask ----------------
__global__ void pool_softmax(float* __restrict__ aw, const int* __restrict__ tok)
{
    const int l = blockIdx.x, b = blockIdx.y;
    float* row = aw + ((long)b * LLAB + l) * SSEQ;
    const int* t = tok + (long)b * SSEQ;

    __shared__ float buf[SSEQ];
    __shared__ float red[33];
    const int tid = threadIdx.x;   // 256

    float mx = -INFINITY;
    for (int s = tid; s < SSEQ; s += 256) {
        int tv = t[s];
        bool bad = (tv == 0) || (tv == 101) || (tv == 102);
        float v = row[s] + (bad ? -INFINITY : 0.f);
        buf[s] = v;
        mx = fmaxf(mx, v);
    }
    for (int o = 16; o; o >>= 1) mx = fmaxf(mx, __shfl_xor_sync(0xffffffffu, mx, o));
    if ((tid & 31) == 0) red[tid >> 5] = mx;
    __syncthreads();
    if (tid < 32) {
        float v = (tid < 8) ? red[tid] : -INFINITY;
        for (int o = 16; o; o >>= 1) v = fmaxf(v, __shfl_xor_sync(0xffffffffu, v, o));
        if (tid == 0) red[32] = v;
    }
    __syncthreads();
    mx = red[32];
    __syncthreads();

    float sum = 0.f;
    for (int s = tid; s < SSEQ; s += 256) {
        float e = expf(buf[s] - mx);
        buf[s] = e;
        sum += e;
    }
    for (int o = 16; o; o >>= 1) sum += __shfl_xor_sync(0xffffffffu, sum, o);
    if ((tid & 31) == 0) red[tid >> 5] = sum;
    __syncthreads();
    if (tid < 32) {
        float v = (tid < 8) ? red[tid] : 0.f;
        for (int o = 16; o; o >>= 1) v += __shfl_xor_sync(0xffffffffu, v, o);
        if (tid == 0) red[32] = v;
    }
    __syncthreads();
    float inv = 1.f / red[32];

    for (int s = tid; s < SSEQ; s += 256) row[s] = buf[s] * inv;
}

// ---------------- final split-K reduce + sigmoid ----------------
__global__ void final_reduce(const float* __restrict__ part,
                             const float* __restrict__ bout,
                             float* __restrict__ out)
{
    int i = blockIdx.x * blockDim.x + threadIdx.x;
    if (i >= BBAT * LLAB) return;
    int l = i % LLAB;
    float s = bout[l];
    #pragma unroll
    for (int z = 0; z < NSPLIT; z++) s += part[z * (BBAT * LLAB) + i];
    out[i] = 1.f / (1.f + expf(-s));
}

// ---------------- host orchestration ----------------
extern "C" void kernel_launch(void* const* d_in, const int* in_sizes, int n_in,
                              void* d_out, int out_size)
{
    const int*   inputs      = (const int*)  d_in[0];
    const float* text_hidden = (const float*)d_in[1];
    const float* label_feat  = (const float*)d_in[2];
    const int*   amask       = (const int*)  d_in[3];
    const float* Wt   = (const float*)d_in[4];
    const float* bt   = (const float*)d_in[5];
    const float* Wl   = (const float*)d_in[6];
    const float* bl   = (const float*)d_in[7];
    const float* WK   = (const float*)d_in[8];
    const float* WQ   = (const float*)d_in[9];
    const float* WV   = (const float*)d_in[10];
    const float* PA   = (const float*)d_in[11];
    const float* PM   = (const float*)d_in[12];
    const float* WA   = (const float*)d_in[13];
    const float* Wout = (const float*)d_in[14];
    const float* bout = (const float*)d_in[15];
    float* out = (float*)d_out;

    float *te, *le, *Kb, *paq, *pmv, *mm, *aw, *feat, *part, *wqe, *wve;
    cudaGetSymbolAddress((void**)&te,   g_text_enc);
    cudaGetSymbolAddress((void**)&le,   g_le);
    cudaGetSymbolAddress((void**)&Kb,   g_Kb);
    cudaGetSymbolAddress((void**)&paq,  g_PAQ);
    cudaGetSymbolAddress((void**)&pmv,  g_PMV);
    cudaGetSymbolAddress((void**)&mm,   g_M);
    cudaGetSymbolAddress((void**)&aw,   g_aw);
    cudaGetSymbolAddress((void**)&feat, g_feat);
    cudaGetSymbolAddress((void**)&part, g_part);
    cudaGetSymbolAddress((void**)&wqe,  g_WQe);
    cudaGetSymbolAddress((void**)&wve,  g_WVe);

    cudaFuncSetAttribute(attn_fused, cudaFuncAttributeMaxDynamicSharedMemorySize, ATTN_SMEM);

    // effective weights (tiny)
    prep_eff<<<dim3(24, 2), 256>>>(WQ, WV, PA, PM, wqe, wve);

    // text_enc = tanh(text_hidden @ Wt^T + bt)   [16384, 256] K=768
    tgemm_g<128, 128, 16, 64, 32, 1, false><<<dim3(cdiv(HIDC, 128), cdiv(BBAT * SSEQ, 128), 1), 256>>>(
        text_hidden, Wt, bt, te,
        BBAT * SSEQ, HIDC, DBERT, DBERT, DBERT, HIDC, 0, 0, 0);

    // le = label_feat @ Wl^T + bl   [600, 256] K=768
    tgemm_g<128, 128, 16, 64, 32, 0, false><<<dim3(cdiv(HIDC, 128), cdiv(LLAB, 128), 1), 256>>>(
        label_feat, Wl, bl, le,
        LLAB, HIDC, DBERT, DBERT, DBERT, HIDC, 0, 0, 0);

    for (int layer = 0; layer < 2; layer++) {
        proj_fused<<<dim3(cdiv(HIDC, 64), cdiv(NN3, 64), 9), 128>>>(
            le, WK, wqe, wve, Kb, paq, pmv);

        attn_fused<<<dim3(cdiv(LLAB, 32), NHEAD), 256, ATTN_SMEM>>>(
            paq, Kb, pmv, amask, mm);

        wa_fused<<<dim3(cdiv(HIDC, 64), cdiv(NN3, 64), 3), 128>>>(mm, WA, le);
    }

    // aw[b,l,s] = le[l,:]·te[b,s,:]   [600,512] K=256, batched over b
    tgemm_g<128, 128, 16, 64, 32, 0, false><<<dim3(cdiv(SSEQ, 128), cdiv(LLAB, 128), BBAT), 256>>>(
        le, te, nullptr, aw,
        LLAB, SSEQ, HIDC, HIDC, HIDC, SSEQ,
        0, (long)SSEQ * HIDC, (long)LLAB * SSEQ);

    pool_softmax<<<dim3(LLAB, BBAT), 256>>>(aw, inputs);

    // features[b,l,e] = sum_s aw[b,l,s] * te[b,s,e]  [600,256] K=512 (NN)
    tgemm_g<128, 128, 16, 64, 32, 0, true><<<dim3(cdiv(HIDC, 128), cdiv(LLAB, 128), BBAT), 256>>>(
        aw, te, nullptr, feat,
        LLAB, HIDC, SSEQ, SSEQ, HIDC, HIDC,
        (long)LLAB * SSEQ, (long)SSEQ * HIDC, (long)LLAB * HIDC);

    // final GEMM, split-K 64: M=32, N=600, K=2400/slice
    {
        const int KS = (LLAB * HIDC) / NSPLIT;   // 2400
        tgemm_g<32, 128, 16, 16, 32, 0, false><<<dim3(cdiv(LLAB, 128), 1, NSPLIT), 256>>>(
            feat, Wout, nullptr, part,
            BBAT, LLAB, KS,
            LLAB * HIDC, LLAB * HIDC, LLAB,
            (long)KS, (long)KS, (long)BBAT * LLAB);
    }

    final_reduce<<<cdiv(BBAT * LLAB, 256), 256>>>(part, bout, out);
}